// round 15
// baseline (speedup 1.0000x reference)
#include <cuda_runtime.h>
#include <cuda_fp16.h>

#define D_MODEL 256
#define D_CLIP 768
#define NHEAD 8
#define HEAD_DIM 32
#define Q_LEN 100
#define BATCH 32
#define T_LEN 1203
#define T_PAD 1216
#define NROWS (Q_LEN * BATCH)   // 3200
#define LOG2E 1.4426950408889634f
#define TT 64
#define NCH (T_PAD / TT)        // 19 chunks
#define VT_PITCH 72             // 64 + 8 halfs: conflict-free V^T reads
#define OV_PITCH 72             // floats; <=2-way LDS conflicts

// attn smem buffer layout (bytes, per buffer)
#define SB_KHI 0
#define SB_KLO 4096
#define SB_VHI 8192
#define SB_VLO 12800
#define SB_OV  17408
#define SB_STRIDE 35840         // per-buffer bytes; x2 = 71680

typedef unsigned long long u64;
typedef unsigned int u32;

// ---- scratch (device globals) ----
__device__ __half g_Khi[NHEAD * T_PAD * HEAD_DIM];   // K * scale*(1-a_h)*log2e, split hi
__device__ __half g_Klo[NHEAD * T_PAD * HEAD_DIM];
__device__ __half g_Vthi[NHEAD * HEAD_DIM * T_PAD];  // V transposed [h][d][t], split
__device__ __half g_Vtlo[NHEAD * HEAD_DIM * T_PAD];
__device__ __half g_Qhi[BATCH * NHEAD * Q_LEN * HEAD_DIM];
__device__ __half g_Qlo[BATCH * NHEAD * Q_LEN * HEAD_DIM];
__device__ float g_AT[BATCH * NHEAD * Q_LEN * HEAD_DIM];  // normalized attn out
__device__ float g_OOV[BATCH * Q_LEN * T_PAD];            // aligned-repacked oov
// packed transposed weights
__device__ float g_WqT4[D_MODEL * D_MODEL];
__device__ float g_WkT4[D_MODEL * D_CLIP];
__device__ float g_WvT4[D_MODEL * D_CLIP];
__device__ float g_WoT4[D_MODEL * D_MODEL];

// ---- packed fp32x2 helpers ----
__device__ __forceinline__ void unpk2(u64 v, float& lo, float& hi) {
    asm("mov.b64 {%0, %1}, %2;" : "=f"(lo), "=f"(hi) : "l"(v));
}
__device__ __forceinline__ u64 fma2(u64 a, u64 b, u64 c) {
    u64 d; asm("fma.rn.f32x2 %0, %1, %2, %3;" : "=l"(d) : "l"(a), "l"(b), "l"(c)); return d;
}
__device__ __forceinline__ float hsum2(u64 v) { float lo, hi; unpk2(v, lo, hi); return lo + hi; }
__device__ __forceinline__ float ex2(float x) {
    float r; asm("ex2.approx.f32 %0, %1;" : "=f"(r) : "f"(x)); return r;
}
__device__ __forceinline__ u32 f2h2(float flo, float fhi) {
    u32 r; asm("cvt.rn.f16x2.f32 %0, %1, %2;" : "=r"(r) : "f"(fhi), "f"(flo)); return r;
}
__device__ __forceinline__ float2 h22f2(u32 h) {
    __half2 hh = *reinterpret_cast<__half2*>(&h);
    return __half22float2(hh);
}
__device__ __forceinline__ void mma16816(float* d, const u32* a, u32 b0, u32 b1) {
    asm volatile("mma.sync.aligned.m16n8k16.row.col.f32.f16.f16.f32 "
        "{%0,%1,%2,%3}, {%4,%5,%6,%7}, {%8,%9}, {%0,%1,%2,%3};"
        : "+f"(d[0]), "+f"(d[1]), "+f"(d[2]), "+f"(d[3])
        : "r"(a[0]), "r"(a[1]), "r"(a[2]), "r"(a[3]), "r"(b0), "r"(b1));
}
__device__ __forceinline__ void split16(float v, __half& hi, __half& lo) {
    hi = __float2half_rn(v);
    lo = __float2half_rn(v - __half2float(hi));
}
__device__ __forceinline__ void cpa16(u32 dst, const void* src) {
    asm volatile("cp.async.ca.shared.global [%0], [%1], 16;" :: "r"(dst), "l"(src));
}
#define CP_COMMIT() asm volatile("cp.async.commit_group;" ::: "memory")
#define CP_WAIT(N)  asm volatile("cp.async.wait_group %0;" :: "n"(N) : "memory")

// ============================================================================
// Kernel 0a: pack weights + zero-fill K/V padding rows (t in [1203,1216)).
// ============================================================================
__global__ void pack_all_kernel(const float* __restrict__ Wq, const float* __restrict__ Wk,
                                const float* __restrict__ Wv, const float* __restrict__ Wo)
{
    const int idx = blockIdx.x * blockDim.x + threadIdx.x;
    if (idx < 131072) {
        const float* src; float* dst; int n4, id;
        if (idx < 16384)       { src = Wq; dst = g_WqT4; n4 = 64;  id = idx; }
        else if (idx < 65536)  { src = Wk; dst = g_WkT4; n4 = 192; id = idx - 16384; }
        else if (idx < 114688) { src = Wv; dst = g_WvT4; n4 = 192; id = idx - 65536; }
        else                   { src = Wo; dst = g_WoT4; n4 = 64;  id = idx - 114688; }
        int j = id / n4, c4 = id - j * n4;
        float4 v = ((const float4*)src)[(size_t)j * n4 + c4];
        ((float4*)dst)[(size_t)c4 * D_MODEL + j] = v;
    } else {
        int p = idx - 131072;                 // 13312 pad halfs (x2 arrays each)
        if (p < 6656) {
            int a = p / 3328, r = p % 3328;   // K pads: h, t in [1203,1216), d
            int h = r / 416, rr = r % 416;
            int t = T_LEN + rr / 32, d = rr % 32;
            __half* dst = a ? g_Klo : g_Khi;
            dst[((size_t)h * T_PAD + t) * 32 + d] = __half(0.0f);
        } else if (p < 13312) {
            int q = p - 6656;
            int a = q / 3328, r = q % 3328;   // Vt pads: row = h*32+d, t
            int row = r / 13, t = T_LEN + r % 13;
            __half* dst = a ? g_Vtlo : g_Vthi;
            dst[(size_t)row * T_PAD + t] = __half(0.0f);
        }
    }
}

// Kernel 0b: repack oov into 16B-aligned rows [b][q][T_PAD]
__global__ void oov_pack_kernel(const float* __restrict__ oov)
{
    const int total = BATCH * Q_LEN * T_LEN;
    for (int idx = blockIdx.x * blockDim.x + threadIdx.x; idx < total; idx += gridDim.x * blockDim.x) {
        int row = idx / T_LEN, t = idx - row * T_LEN;
        g_OOV[(size_t)row * T_PAD + t] = oov[idx];
    }
}

// ============================================================================
// Kernel 1: FUSED projections. Blocks [0,76): K, [76,152): V, [152,552): Q.
// K: l2norm + fold scale*(1-a_h)*log2e, split fp16.
// V: split fp16, stored transposed [h][d][t].  Q: l2norm, split fp16.
// ============================================================================
#define ROWS_KV 16
#define ROWS_Q 8
#define QKV_GRID (152 + NROWS / ROWS_Q)   // 552
__global__ __launch_bounds__(256, 2) void qkv_kernel(
    const float* __restrict__ text, const float* __restrict__ tgt,
    const float* __restrict__ qpos, const float* __restrict__ bk,
    const float* __restrict__ bv, const float* __restrict__ bq,
    const float* __restrict__ lsp)
{
    extern __shared__ float sbuf[];   // 48 KB
    const int bid = blockIdx.x;
    const int tid = threadIdx.x;
    const int j = tid, head = j >> 5, lane = j & 31;

    if (bid < 152) {
        // ---------------- K/V role ----------------
        const int isV = bid >= 76;
        const int t0 = (isV ? bid - 76 : bid) * ROWS_KV;
        const int nrows = min(ROWS_KV, T_LEN - t0);

        for (int idx = tid; idx < ROWS_KV * (D_CLIP / 4); idx += 256) {
            int r = idx / (D_CLIP / 4);
            float4 v = make_float4(0.f, 0.f, 0.f, 0.f);
            if (r < nrows) {
                int c4 = idx - r * (D_CLIP / 4);
                v = ((const float4*)(text + (size_t)(t0 + r) * D_CLIP))[c4];
            }
            ((float4*)sbuf)[idx] = v;
        }
        __syncthreads();

        u64 aA[ROWS_KV], aB[ROWS_KV];
#pragma unroll
        for (int r = 0; r < ROWS_KV; ++r) { aA[r] = aB[r] = 0ull; }

        const ulonglong2* wp = ((const ulonglong2*)(isV ? g_WvT4 : g_WkT4)) + j;
#pragma unroll 4
        for (int c4 = 0; c4 < D_CLIP / 4; ++c4) {
            ulonglong2 w4 = wp[(size_t)c4 * D_MODEL];
#pragma unroll
            for (int r = 0; r < ROWS_KV; ++r) {
                ulonglong2 x = *(const ulonglong2*)(sbuf + r * D_CLIP + 4 * c4);
                aA[r] = fma2(x.x, w4.x, aA[r]);
                aB[r] = fma2(x.y, w4.y, aB[r]);
            }
        }

        if (isV) {
            const float bvj = bv[j];
            for (int r = 0; r < nrows; ++r) {
                int t = t0 + r;
                float v = hsum2(aA[r]) + hsum2(aB[r]) + bvj;
                __half hi, lo; split16(v, hi, lo);
                size_t o = (size_t)(head * 32 + lane) * T_PAD + t;
                g_Vthi[o] = hi; g_Vtlo[o] = lo;
            }
        } else {
            const float scale = fminf(expf(lsp[0]), 100.0f);
            const float kfac = scale * (1.0f - (float)head * (1.0f / 7.0f)) * LOG2E;
            const float bkj = bk[j];
            for (int r = 0; r < nrows; ++r) {
                float kk = hsum2(aA[r]) + hsum2(aB[r]) + bkj;
                float ss = kk * kk;
#pragma unroll
                for (int off = 16; off > 0; off >>= 1) ss += __shfl_xor_sync(0xffffffffu, ss, off);
                float val = kk / fmaxf(sqrtf(ss), 1e-6f) * kfac;
                __half hi, lo; split16(val, hi, lo);
                size_t o = ((size_t)head * T_PAD + t0 + r) * 32 + lane;
                g_Khi[o] = hi; g_Klo[o] = lo;
            }
        }
    } else {
        // ---------------- Q role ----------------
        const int r0 = (bid - 152) * ROWS_Q;

        for (int idx = tid; idx < ROWS_Q * (D_MODEL / 4); idx += 256) {
            int r = idx >> 6, c4 = idx & 63;
            const float4 a = ((const float4*)(tgt  + (size_t)(r0 + r) * D_MODEL))[c4];
            const float4 p = ((const float4*)(qpos + (size_t)(r0 + r) * D_MODEL))[c4];
            ((float4*)sbuf)[idx] = make_float4(a.x + p.x, a.y + p.y, a.z + p.z, a.w + p.w);
        }
        __syncthreads();

        u64 aA[ROWS_Q], aB[ROWS_Q];
#pragma unroll
        for (int r = 0; r < ROWS_Q; ++r) { aA[r] = aB[r] = 0ull; }

        const ulonglong2* wqp = ((const ulonglong2*)g_WqT4) + j;
#pragma unroll 4
        for (int c4 = 0; c4 < D_MODEL / 4; ++c4) {
            ulonglong2 w4 = wqp[(size_t)c4 * D_MODEL];
#pragma unroll
            for (int r = 0; r < ROWS_Q; ++r) {
                ulonglong2 x = *(const ulonglong2*)(sbuf + r * D_MODEL + 4 * c4);
                aA[r] = fma2(x.x, w4.x, aA[r]);
                aB[r] = fma2(x.y, w4.y, aB[r]);
            }
        }

        const float bqj = bq[j];
        for (int r = 0; r < ROWS_Q; ++r) {
            float qq = hsum2(aA[r]) + hsum2(aB[r]) + bqj;
            float ss = qq * qq;
#pragma unroll
            for (int off = 16; off > 0; off >>= 1) ss += __shfl_xor_sync(0xffffffffu, ss, off);
            float val = qq / fmaxf(sqrtf(ss), 1e-6f);
            int row = r0 + r;
            int qi = row >> 5, b = row & 31;
            __half hi, lo; split16(val, hi, lo);
            size_t o = ((size_t)((b * NHEAD) + head) * Q_LEN + qi) * HEAD_DIM + lane;
            g_Qhi[o] = hi; g_Qlo[o] = lo;
        }
    }
}

// ============================================================================
// Kernel 3: HMMA flash attention, double-buffered cp.async staging.
// Block = (h, b, qhalf); 4 warps x m16 queries. Split-fp16 3-MMA GEMMs.
// ============================================================================
__global__ __launch_bounds__(128, 4) void attn_kernel()
{
    const int h = blockIdx.x, b = blockIdx.y, qc = blockIdx.z;
    const int tid = threadIdx.x;
    const int warp = tid >> 5, lane = tid & 31;
    const int g = lane >> 2, c = lane & 3;
    const int q0 = qc * 64 + warp * 16;
    const int r0 = min(q0 + g, Q_LEN - 1);
    const int r1 = min(q0 + g + 8, Q_LEN - 1);

    extern __shared__ __align__(16) char smem_raw[];   // 2 x SB_STRIDE

    const bool use_qk = (h != NHEAD - 1);
    const bool use_ov = (h != 0);
    const float ap = (float)h * (1.0f / 7.0f) * LOG2E;

    // ---- Q a-frags (2 ksteps x 4 regs, hi+lo) ----
    u32 qa_hi[2][4], qa_lo[2][4];
    {
        const __half* Qh = g_Qhi + (size_t)(b * NHEAD + h) * Q_LEN * HEAD_DIM;
        const __half* Ql = g_Qlo + (size_t)(b * NHEAD + h) * Q_LEN * HEAD_DIM;
#pragma unroll
        for (int ks = 0; ks < 2; ++ks) {
            int col = 16 * ks + 2 * c;
            qa_hi[ks][0] = *(const u32*)&Qh[r0 * 32 + col];
            qa_hi[ks][1] = *(const u32*)&Qh[r1 * 32 + col];
            qa_hi[ks][2] = *(const u32*)&Qh[r0 * 32 + col + 8];
            qa_hi[ks][3] = *(const u32*)&Qh[r1 * 32 + col + 8];
            qa_lo[ks][0] = *(const u32*)&Ql[r0 * 32 + col];
            qa_lo[ks][1] = *(const u32*)&Ql[r1 * 32 + col];
            qa_lo[ks][2] = *(const u32*)&Ql[r0 * 32 + col + 8];
            qa_lo[ks][3] = *(const u32*)&Ql[r1 * 32 + col + 8];
        }
    }

    float O[4][4];
#pragma unroll
    for (int dt = 0; dt < 4; ++dt)
#pragma unroll
        for (int e = 0; e < 4; ++e) O[dt][e] = 0.f;
    float m0 = -1e30f, m1 = -1e30f, l0 = 0.f, l1 = 0.f;

    const int kbase = g * 32 + 2 * c;
    const int vbase = g * VT_PITCH + 2 * c;

    // ---- async stage of one 64-key chunk into buffer bi ----
    auto stage = [&](int ci, int bi) {
        char* base = smem_raw + bi * SB_STRIDE;
        const int t0 = ci * TT;
        u32 sb = (u32)__cvta_generic_to_shared(base);
        const char* srcKh = (const char*)(g_Khi + ((size_t)h * T_PAD + t0) * 32);
        const char* srcKl = (const char*)(g_Klo + ((size_t)h * T_PAD + t0) * 32);
#pragma unroll
        for (int it = 0; it < 2; ++it) {
            int idx = tid + it * 128;
            cpa16(sb + SB_KHI + idx * 16, srcKh + idx * 16);
            cpa16(sb + SB_KLO + idx * 16, srcKl + idx * 16);
        }
#pragma unroll
        for (int it = 0; it < 2; ++it) {
            int idx = tid + it * 128;
            int d = idx >> 3, s = idx & 7;
            size_t srcoff = ((size_t)(h * 32 + d) * T_PAD + t0) * 2 + s * 16;
            cpa16(sb + SB_VHI + d * 144 + s * 16, (const char*)g_Vthi + srcoff);
            cpa16(sb + SB_VLO + d * 144 + s * 16, (const char*)g_Vtlo + srcoff);
        }
        if (use_ov) {
#pragma unroll
            for (int it = 0; it < 8; ++it) {
                int idx = tid + it * 128;
                int r = idx >> 4, c4 = idx & 15;
                int qrow = min(qc * 64 + r, Q_LEN - 1);
                const char* src = (const char*)(g_OOV + (size_t)(b * Q_LEN + qrow) * T_PAD + t0) + c4 * 16;
                cpa16(sb + SB_OV + r * 288 + c4 * 16, src);
            }
        }
        CP_COMMIT();
    };

    stage(0, 0);

    for (int ci = 0; ci < NCH; ++ci) {
        const int t0 = ci * TT;
        const int bi = ci & 1;
        if (ci + 1 < NCH) { stage(ci + 1, bi ^ 1); CP_WAIT(1); }
        else              { CP_WAIT(0); }
        __syncthreads();

        char* base = smem_raw + bi * SB_STRIDE;
        const __half* sKhi = (const __half*)(base + SB_KHI);
        const __half* sKlo = (const __half*)(base + SB_KLO);
        const __half* sVhi = (const __half*)(base + SB_VHI);
        const __half* sVlo = (const __half*)(base + SB_VLO);
        const float*  sOV  = (const float*)(base + SB_OV);
        const float* so0 = sOV + (warp * 16 + g) * OV_PITCH + 2 * c;
        const float* so1 = so0 + 8 * OV_PITCH;

        // ---- S = Q K^T (8 n-tiles of 8 keys) ----
        float s[8][4];
#pragma unroll
        for (int j = 0; j < 8; ++j)
#pragma unroll
            for (int e = 0; e < 4; ++e) s[j][e] = 0.f;

        if (use_qk) {
#pragma unroll
            for (int j = 0; j < 8; ++j) {
#pragma unroll
                for (int ks = 0; ks < 2; ++ks) {
                    const __half* kh = sKhi + j * 256 + kbase + 16 * ks;
                    const __half* kl = sKlo + j * 256 + kbase + 16 * ks;
                    u32 bh0 = *(const u32*)kh;
                    u32 bh1 = *(const u32*)(kh + 8);
                    u32 bl0 = *(const u32*)kl;
                    u32 bl1 = *(const u32*)(kl + 8);
                    mma16816(s[j], qa_hi[ks], bh0, bh1);
                    mma16816(s[j], qa_hi[ks], bl0, bl1);
                    mma16816(s[j], qa_lo[ks], bh0, bh1);
                }
            }
        }
        if (use_ov) {
#pragma unroll
            for (int j = 0; j < 8; ++j) {
                float2 o0 = *(const float2*)(so0 + 8 * j);
                float2 o1 = *(const float2*)(so1 + 8 * j);
                s[j][0] = fmaf(ap, o0.x, s[j][0]);
                s[j][1] = fmaf(ap, o0.y, s[j][1]);
                s[j][2] = fmaf(ap, o1.x, s[j][2]);
                s[j][3] = fmaf(ap, o1.y, s[j][3]);
            }
        }
        if (t0 + TT > T_LEN) {
#pragma unroll
            for (int j = 0; j < 8; ++j) {
                int t = t0 + 8 * j + 2 * c;
                if (t >= T_LEN)     { s[j][0] = -1e30f; s[j][2] = -1e30f; }
                if (t + 1 >= T_LEN) { s[j][1] = -1e30f; s[j][3] = -1e30f; }
            }
        }

        // ---- online softmax (log2 domain) ----
        float cm0 = s[0][0], cm1 = s[0][2];
#pragma unroll
        for (int j = 0; j < 8; ++j) {
            cm0 = fmaxf(cm0, fmaxf(s[j][0], s[j][1]));
            cm1 = fmaxf(cm1, fmaxf(s[j][2], s[j][3]));
        }
        cm0 = fmaxf(cm0, __shfl_xor_sync(0xffffffffu, cm0, 1));
        cm0 = fmaxf(cm0, __shfl_xor_sync(0xffffffffu, cm0, 2));
        cm1 = fmaxf(cm1, __shfl_xor_sync(0xffffffffu, cm1, 1));
        cm1 = fmaxf(cm1, __shfl_xor_sync(0xffffffffu, cm1, 2));
        float nm0 = fmaxf(m0, cm0), nm1 = fmaxf(m1, cm1);
        float rs0 = ex2(m0 - nm0), rs1 = ex2(m1 - nm1);
        m0 = nm0; m1 = nm1;
        l0 *= rs0; l1 *= rs1;
#pragma unroll
        for (int dt = 0; dt < 4; ++dt) {
            O[dt][0] *= rs0; O[dt][1] *= rs0;
            O[dt][2] *= rs1; O[dt][3] *= rs1;
        }
#pragma unroll
        for (int j = 0; j < 8; ++j) {
            s[j][0] = ex2(s[j][0] - m0);
            s[j][1] = ex2(s[j][1] - m0);
            s[j][2] = ex2(s[j][2] - m1);
            s[j][3] = ex2(s[j][3] - m1);
            l0 += s[j][0] + s[j][1];
            l1 += s[j][2] + s[j][3];
        }

        // ---- O += P V ----
#pragma unroll
        for (int ks = 0; ks < 4; ++ks) {
            const int j0 = 2 * ks, j1 = 2 * ks + 1;
            u32 pa_hi[4], pa_lo[4];
            pa_hi[0] = f2h2(s[j0][0], s[j0][1]);
            pa_hi[1] = f2h2(s[j0][2], s[j0][3]);
            pa_hi[2] = f2h2(s[j1][0], s[j1][1]);
            pa_hi[3] = f2h2(s[j1][2], s[j1][3]);
#pragma unroll
            for (int e = 0; e < 4; ++e) {
                const int jj = (e < 2) ? j0 : j1;
                const int base2 = (e & 1) ? 2 : 0;
                float2 hf = h22f2(pa_hi[e]);
                pa_lo[e] = f2h2(s[jj][base2] - hf.x, s[jj][base2 + 1] - hf.y);
            }
#pragma unroll
            for (int dt = 0; dt < 4; ++dt) {
                const __half* vh = sVhi + dt * 8 * VT_PITCH + vbase + 16 * ks;
                const __half* vl = sVlo + dt * 8 * VT_PITCH + vbase + 16 * ks;
                u32 bh0 = *(const u32*)vh;
                u32 bh1 = *(const u32*)(vh + 8);
                u32 bl0 = *(const u32*)vl;
                u32 bl1 = *(const u32*)(vl + 8);
                mma16816(O[dt], pa_hi, bh0, bh1);
                mma16816(O[dt], pa_hi, bl0, bl1);
                mma16816(O[dt], pa_lo, bh0, bh1);
            }
        }
        __syncthreads();   // all reads of buf bi done before it is re-staged
    }

    // ---- epilogue ----
    l0 += __shfl_xor_sync(0xffffffffu, l0, 1);
    l0 += __shfl_xor_sync(0xffffffffu, l0, 2);
    l1 += __shfl_xor_sync(0xffffffffu, l1, 1);
    l1 += __shfl_xor_sync(0xffffffffu, l1, 2);
    const float inv0 = 1.0f / l0, inv1 = 1.0f / l1;
    float* dstBase = g_AT + (size_t)(b * NHEAD + h) * Q_LEN * HEAD_DIM;
    if (q0 + g < Q_LEN) {
        float* d0 = dstBase + (size_t)(q0 + g) * HEAD_DIM + 2 * c;
#pragma unroll
        for (int dt = 0; dt < 4; ++dt)
            *(float2*)(d0 + 8 * dt) = make_float2(O[dt][0] * inv0, O[dt][1] * inv0);
    }
    if (q0 + g + 8 < Q_LEN) {
        float* d1 = dstBase + (size_t)(q0 + g + 8) * HEAD_DIM + 2 * c;
#pragma unroll
        for (int dt = 0; dt < 4; ++dt)
            *(float2*)(d1 + 8 * dt) = make_float2(O[dt][2] * inv1, O[dt][3] * inv1);
    }
}

// ============================================================================
// Kernel 4: output projection + residual + LayerNorm (ROWS 16)
// ============================================================================
#define ROWS_P 16
__global__ __launch_bounds__(256, 2) void proj_kernel(
    const float* __restrict__ tgt, const float* __restrict__ bo,
    const float* __restrict__ ln_g, const float* __restrict__ ln_b, float* __restrict__ out)
{
    __shared__ float s_att[ROWS_P][D_MODEL];
    __shared__ float s_y[ROWS_P][D_MODEL];
    __shared__ float s_mu[ROWS_P], s_rs[ROWS_P];
    const int tid = threadIdx.x;
    const int r0 = blockIdx.x * ROWS_P;
    const int j = tid, head = j >> 5, lane = j & 31;

    for (int r = 0; r < ROWS_P; ++r) {
        int row = r0 + r, qi = row >> 5, b = row & 31;
        s_att[r][j] = g_AT[((size_t)((b * NHEAD) + head) * Q_LEN + qi) * HEAD_DIM + lane];
    }
    __syncthreads();

    u64 accA[ROWS_P], accB[ROWS_P];
#pragma unroll
    for (int r = 0; r < ROWS_P; ++r) { accA[r] = accB[r] = 0ull; }
    const ulonglong2* wop = ((const ulonglong2*)g_WoT4) + j;
#pragma unroll 4
    for (int c4 = 0; c4 < D_MODEL / 4; ++c4) {
        ulonglong2 w4 = wop[(size_t)c4 * D_MODEL];
#pragma unroll
        for (int r = 0; r < ROWS_P; ++r) {
            ulonglong2 x = *(const ulonglong2*)(&s_att[r][4 * c4]);
            accA[r] = fma2(x.x, w4.x, accA[r]);
            accB[r] = fma2(x.y, w4.y, accB[r]);
        }
    }

    const float boj = bo[j];
    for (int r = 0; r < ROWS_P; ++r) {
        int row = r0 + r;
        s_y[r][j] = hsum2(accA[r]) + hsum2(accB[r]) + boj + tgt[(size_t)row * D_MODEL + j];
    }
    __syncthreads();

    {
        const int w = tid >> 5, ln = tid & 31;
#pragma unroll
        for (int rr = 0; rr < 2; ++rr) {
            int r = 2 * w + rr;
            float sval = 0.f, sq = 0.f;
            for (int cc = ln; cc < D_MODEL; cc += 32) { float v = s_y[r][cc]; sval += v; sq += v * v; }
#pragma unroll
            for (int off = 16; off > 0; off >>= 1) {
                sval += __shfl_xor_sync(0xffffffffu, sval, off);
                sq   += __shfl_xor_sync(0xffffffffu, sq, off);
            }
            if (ln == 0) {
                float mu = sval * (1.0f / D_MODEL);
                s_mu[r] = mu;
                s_rs[r] = rsqrtf(sq * (1.0f / D_MODEL) - mu * mu + 1e-5f);
            }
        }
    }
    __syncthreads();

    const float gg = ln_g[j], bb = ln_b[j];
    for (int r = 0; r < ROWS_P; ++r) {
        int row = r0 + r;
        out[(size_t)row * D_MODEL + j] = (s_y[r][j] - s_mu[r]) * s_rs[r] * gg + bb;
    }
}

// ============================================================================
extern "C" void kernel_launch(void* const* d_in, const int* in_sizes, int n_in,
                              void* d_out, int out_size)
{
    const float* tgt  = (const float*)d_in[0];
    const float* text = (const float*)d_in[1];
    const float* qpos = (const float*)d_in[2];
    const float* oov  = (const float*)d_in[3];
    const float* Wq   = (const float*)d_in[4];
    const float* bq   = (const float*)d_in[5];
    const float* Wk   = (const float*)d_in[6];
    const float* bk   = (const float*)d_in[7];
    const float* Wv   = (const float*)d_in[8];
    const float* bv   = (const float*)d_in[9];
    const float* Wo   = (const float*)d_in[10];
    const float* bo   = (const float*)d_in[11];
    const float* lng  = (const float*)d_in[12];
    const float* lnb  = (const float*)d_in[13];
    const float* ls   = (const float*)d_in[14];
    float* out = (float*)d_out;

    pack_all_kernel<<<566, 256>>>(Wq, Wk, Wv, Wo);                     // 1
    oov_pack_kernel<<<2048, 256>>>(oov);                               // 2

    const int qkv_smem = ROWS_KV * D_CLIP * (int)sizeof(float);        // 48 KB
    cudaFuncSetAttribute(qkv_kernel, cudaFuncAttributeMaxDynamicSharedMemorySize, qkv_smem);
    qkv_kernel<<<QKV_GRID, 256, qkv_smem>>>(text, tgt, qpos, bk, bv, bq, ls);  // 3

    const int att_smem = 2 * SB_STRIDE;                                // 71680 B
    cudaFuncSetAttribute(attn_kernel, cudaFuncAttributeMaxDynamicSharedMemorySize, att_smem);
    attn_kernel<<<dim3(NHEAD, BATCH, 2), 128, att_smem>>>();           // 4 <- profiled

    proj_kernel<<<NROWS / ROWS_P, 256>>>(tgt, bo, lng, lnb, out);      // 5
}

// round 16
// speedup vs baseline: 1.2676x; 1.2676x over previous
#include <cuda_runtime.h>
#include <cuda_fp16.h>

#define D_MODEL 256
#define D_CLIP 768
#define NHEAD 8
#define HEAD_DIM 32
#define Q_LEN 100
#define BATCH 32
#define T_LEN 1203
#define T_PAD 1216
#define NROWS (Q_LEN * BATCH)   // 3200
#define LOG2E 1.4426950408889634f
#define TT 64
#define NCH (T_PAD / TT)        // 19 chunks
#define VT_PITCH 72             // 64 + 8 halfs: conflict-free V^T reads
#define OV_PITCH 72             // floats; <=2-way LDS conflicts

// attn smem buffer layout (bytes, per buffer)
#define SB_KHI 0
#define SB_KLO 4096
#define SB_VHI 8192
#define SB_VLO 12800
#define SB_OV  17408
#define SB_STRIDE 35840         // per-buffer bytes; x2 = 71680

typedef unsigned long long u64;
typedef unsigned int u32;

// ---- scratch (device globals) ----
__device__ __half g_Khi[NHEAD * T_PAD * HEAD_DIM];   // K * scale*(1-a_h)*log2e, split hi
__device__ __half g_Klo[NHEAD * T_PAD * HEAD_DIM];
__device__ __half g_Vthi[NHEAD * HEAD_DIM * T_PAD];  // V transposed [h][d][t], split
__device__ __half g_Vtlo[NHEAD * HEAD_DIM * T_PAD];
__device__ __half g_Qhi[BATCH * NHEAD * Q_LEN * HEAD_DIM];
__device__ __half g_Qlo[BATCH * NHEAD * Q_LEN * HEAD_DIM];
__device__ float g_AT[BATCH * NHEAD * Q_LEN * HEAD_DIM];  // normalized attn out
__device__ float g_OOV[BATCH * Q_LEN * T_PAD];            // aligned-repacked oov
// packed transposed weights
__device__ float g_WqT4[D_MODEL * D_MODEL];
__device__ float g_WkT4[D_MODEL * D_CLIP];
__device__ float g_WvT4[D_MODEL * D_CLIP];
__device__ float g_WoT4[D_MODEL * D_MODEL];

// ---- packed fp32x2 helpers ----
__device__ __forceinline__ void unpk2(u64 v, float& lo, float& hi) {
    asm("mov.b64 {%0, %1}, %2;" : "=f"(lo), "=f"(hi) : "l"(v));
}
__device__ __forceinline__ u64 fma2(u64 a, u64 b, u64 c) {
    u64 d; asm("fma.rn.f32x2 %0, %1, %2, %3;" : "=l"(d) : "l"(a), "l"(b), "l"(c)); return d;
}
__device__ __forceinline__ float hsum2(u64 v) { float lo, hi; unpk2(v, lo, hi); return lo + hi; }
__device__ __forceinline__ float ex2(float x) {
    float r; asm("ex2.approx.f32 %0, %1;" : "=f"(r) : "f"(x)); return r;
}
__device__ __forceinline__ u32 f2h2(float flo, float fhi) {
    u32 r; asm("cvt.rn.f16x2.f32 %0, %1, %2;" : "=r"(r) : "f"(fhi), "f"(flo)); return r;
}
__device__ __forceinline__ float2 h22f2(u32 h) {
    __half2 hh = *reinterpret_cast<__half2*>(&h);
    return __half22float2(hh);
}
__device__ __forceinline__ void mma16816(float* d, const u32* a, u32 b0, u32 b1) {
    asm volatile("mma.sync.aligned.m16n8k16.row.col.f32.f16.f16.f32 "
        "{%0,%1,%2,%3}, {%4,%5,%6,%7}, {%8,%9}, {%0,%1,%2,%3};"
        : "+f"(d[0]), "+f"(d[1]), "+f"(d[2]), "+f"(d[3])
        : "r"(a[0]), "r"(a[1]), "r"(a[2]), "r"(a[3]), "r"(b0), "r"(b1));
}
__device__ __forceinline__ void split16(float v, __half& hi, __half& lo) {
    hi = __float2half_rn(v);
    lo = __float2half_rn(v - __half2float(hi));
}
__device__ __forceinline__ void cpa16(u32 dst, const void* src) {
    asm volatile("cp.async.ca.shared.global [%0], [%1], 16;" :: "r"(dst), "l"(src));
}
#define CP_COMMIT() asm volatile("cp.async.commit_group;" ::: "memory")
#define CP_WAIT(N)  asm volatile("cp.async.wait_group %0;" :: "n"(N) : "memory")

// ============================================================================
// Kernel 0: pack weights + zero-fill K/V pads + repack oov (one launch).
// ============================================================================
__global__ void pack_all_kernel(const float* __restrict__ Wq, const float* __restrict__ Wk,
                                const float* __restrict__ Wv, const float* __restrict__ Wo,
                                const float* __restrict__ oov)
{
    const int idx = blockIdx.x * blockDim.x + threadIdx.x;
    if (idx < 131072) {
        const float* src; float* dst; int n4, id;
        if (idx < 16384)       { src = Wq; dst = g_WqT4; n4 = 64;  id = idx; }
        else if (idx < 65536)  { src = Wk; dst = g_WkT4; n4 = 192; id = idx - 16384; }
        else if (idx < 114688) { src = Wv; dst = g_WvT4; n4 = 192; id = idx - 65536; }
        else                   { src = Wo; dst = g_WoT4; n4 = 64;  id = idx - 114688; }
        int j = id / n4, c4 = id - j * n4;
        float4 v = ((const float4*)src)[(size_t)j * n4 + c4];
        ((float4*)dst)[(size_t)c4 * D_MODEL + j] = v;
    } else if (idx < 144384) {
        int p = idx - 131072;                 // 13312 pad halfs (x2 arrays each)
        if (p < 6656) {
            int a = p / 3328, r = p % 3328;   // K pads: h, t in [1203,1216), d
            int h = r / 416, rr = r % 416;
            int t = T_LEN + rr / 32, d = rr % 32;
            __half* dst = a ? g_Klo : g_Khi;
            dst[((size_t)h * T_PAD + t) * 32 + d] = __half(0.0f);
        } else {
            int q = p - 6656;
            int a = q / 3328, r = q % 3328;   // Vt pads: row = h*32+d, t
            int row = r / 13, t = T_LEN + r % 13;
            __half* dst = a ? g_Vtlo : g_Vthi;
            dst[(size_t)row * T_PAD + t] = __half(0.0f);
        }
    }
    // oov repack (grid-stride; independent of the above)
    const int total = BATCH * Q_LEN * T_LEN;
    for (int i = idx; i < total; i += gridDim.x * blockDim.x) {
        int row = i / T_LEN, t = i - row * T_LEN;
        g_OOV[(size_t)row * T_PAD + t] = oov[i];
    }
}

// ============================================================================
// Kernel 1: K or V projection (ROWS 16, dynamic smem). K: l2norm + fold
// scale*(1-a_h)*log2e, split fp16. V: split fp16, stored transposed [h][d][t].
// ============================================================================
#define ROWS_KV 16
__global__ __launch_bounds__(256, 2) void kv_kernel(
    const float* __restrict__ text, const float* __restrict__ bk,
    const float* __restrict__ bv, const float* __restrict__ lsp)
{
    extern __shared__ float s_text[];   // [ROWS_KV][768] = 48 KB
    const int tid = threadIdx.x;
    const int t0 = blockIdx.x * ROWS_KV;
    const int isV = blockIdx.y;
    const int nrows = min(ROWS_KV, T_LEN - t0);

    for (int idx = tid; idx < ROWS_KV * (D_CLIP / 4); idx += 256) {
        int r = idx / (D_CLIP / 4);
        float4 v = make_float4(0.f, 0.f, 0.f, 0.f);
        if (r < nrows) {
            int c4 = idx - r * (D_CLIP / 4);
            v = ((const float4*)(text + (size_t)(t0 + r) * D_CLIP))[c4];
        }
        ((float4*)s_text)[idx] = v;
    }
    __syncthreads();

    const int j = tid, head = j >> 5, lane = j & 31;
    u64 aA[ROWS_KV], aB[ROWS_KV];
#pragma unroll
    for (int r = 0; r < ROWS_KV; ++r) { aA[r] = aB[r] = 0ull; }

    const ulonglong2* wp = ((const ulonglong2*)(isV ? g_WvT4 : g_WkT4)) + j;
#pragma unroll 2
    for (int c4 = 0; c4 < D_CLIP / 4; ++c4) {
        ulonglong2 w4 = wp[(size_t)c4 * D_MODEL];
#pragma unroll
        for (int r = 0; r < ROWS_KV; ++r) {
            ulonglong2 x = *(const ulonglong2*)(s_text + r * D_CLIP + 4 * c4);
            aA[r] = fma2(x.x, w4.x, aA[r]);
            aB[r] = fma2(x.y, w4.y, aB[r]);
        }
    }

    if (isV) {
        const float bvj = bv[j];
        for (int r = 0; r < nrows; ++r) {
            int t = t0 + r;
            float v = hsum2(aA[r]) + hsum2(aB[r]) + bvj;
            __half hi, lo; split16(v, hi, lo);
            size_t o = (size_t)(head * 32 + lane) * T_PAD + t;
            g_Vthi[o] = hi; g_Vtlo[o] = lo;
        }
    } else {
        const float scale = fminf(expf(lsp[0]), 100.0f);
        const float kfac = scale * (1.0f - (float)head * (1.0f / 7.0f)) * LOG2E;
        const float bkj = bk[j];
        for (int r = 0; r < nrows; ++r) {
            float kk = hsum2(aA[r]) + hsum2(aB[r]) + bkj;
            float ss = kk * kk;
#pragma unroll
            for (int off = 16; off > 0; off >>= 1) ss += __shfl_xor_sync(0xffffffffu, ss, off);
            float val = kk / fmaxf(sqrtf(ss), 1e-6f) * kfac;
            __half hi, lo; split16(val, hi, lo);
            size_t o = ((size_t)head * T_PAD + t0 + r) * 32 + lane;
            g_Khi[o] = hi; g_Klo[o] = lo;
        }
    }
}

// ============================================================================
// Kernel 2: Q projection + l2norm, split fp16, [b][h][q][d]  (ROWS 16)
// ============================================================================
#define ROWS_Q 16
__global__ __launch_bounds__(256, 2) void q_kernel(
    const float* __restrict__ tgt, const float* __restrict__ qpos,
    const float* __restrict__ bq)
{
    __shared__ float s_in[ROWS_Q][D_MODEL];   // 16 KB
    const int tid = threadIdx.x;
    const int r0 = blockIdx.x * ROWS_Q;

    for (int idx = tid; idx < ROWS_Q * (D_MODEL / 4); idx += 256) {
        int r = idx >> 6, c4 = idx & 63;
        const float4 a = ((const float4*)(tgt  + (size_t)(r0 + r) * D_MODEL))[c4];
        const float4 p = ((const float4*)(qpos + (size_t)(r0 + r) * D_MODEL))[c4];
        ((float4*)(&s_in[r][0]))[c4] = make_float4(a.x + p.x, a.y + p.y, a.z + p.z, a.w + p.w);
    }
    __syncthreads();

    const int j = tid, head = j >> 5, lane = j & 31;
    u64 aA[ROWS_Q], aB[ROWS_Q];
#pragma unroll
    for (int r = 0; r < ROWS_Q; ++r) { aA[r] = aB[r] = 0ull; }

    const ulonglong2* wqp = ((const ulonglong2*)g_WqT4) + j;
#pragma unroll 2
    for (int c4 = 0; c4 < D_MODEL / 4; ++c4) {
        ulonglong2 w4 = wqp[(size_t)c4 * D_MODEL];
#pragma unroll
        for (int r = 0; r < ROWS_Q; ++r) {
            ulonglong2 x = *(const ulonglong2*)(&s_in[r][4 * c4]);
            aA[r] = fma2(x.x, w4.x, aA[r]);
            aB[r] = fma2(x.y, w4.y, aB[r]);
        }
    }

    const float bqj = bq[j];
    for (int r = 0; r < ROWS_Q; ++r) {
        float qq = hsum2(aA[r]) + hsum2(aB[r]) + bqj;
        float ss = qq * qq;
#pragma unroll
        for (int off = 16; off > 0; off >>= 1) ss += __shfl_xor_sync(0xffffffffu, ss, off);
        float val = qq / fmaxf(sqrtf(ss), 1e-6f);
        int row = r0 + r;
        int qi = row >> 5, b = row & 31;
        __half hi, lo; split16(val, hi, lo);
        size_t o = ((size_t)((b * NHEAD) + head) * Q_LEN + qi) * HEAD_DIM + lane;
        g_Qhi[o] = hi; g_Qlo[o] = lo;
    }
}

// ============================================================================
// Kernel 3: HMMA flash attention, double-buffered cp.async staging.
// Block = (h, b, qhalf); 4 warps x m16 queries. Split-fp16 3-MMA GEMMs.
// Fully-out-of-range warps skip compute (stage+sync only).
// ============================================================================
__global__ __launch_bounds__(128, 3) void attn_kernel()
{
    const int h = blockIdx.x, b = blockIdx.y, qc = blockIdx.z;
    const int tid = threadIdx.x;
    const int warp = tid >> 5, lane = tid & 31;
    const int g = lane >> 2, c = lane & 3;
    const int q0 = qc * 64 + warp * 16;
    const bool warp_active = (q0 < Q_LEN);
    const int r0 = min(q0 + g, Q_LEN - 1);
    const int r1 = min(q0 + g + 8, Q_LEN - 1);

    extern __shared__ __align__(16) char smem_raw[];   // 2 x SB_STRIDE

    const bool use_qk = (h != NHEAD - 1);
    const bool use_ov = (h != 0);
    const float ap = (float)h * (1.0f / 7.0f) * LOG2E;

    // ---- Q a-frags (2 ksteps x 4 regs, hi+lo) ----
    u32 qa_hi[2][4], qa_lo[2][4];
    {
        const __half* Qh = g_Qhi + (size_t)(b * NHEAD + h) * Q_LEN * HEAD_DIM;
        const __half* Ql = g_Qlo + (size_t)(b * NHEAD + h) * Q_LEN * HEAD_DIM;
#pragma unroll
        for (int ks = 0; ks < 2; ++ks) {
            int col = 16 * ks + 2 * c;
            qa_hi[ks][0] = *(const u32*)&Qh[r0 * 32 + col];
            qa_hi[ks][1] = *(const u32*)&Qh[r1 * 32 + col];
            qa_hi[ks][2] = *(const u32*)&Qh[r0 * 32 + col + 8];
            qa_hi[ks][3] = *(const u32*)&Qh[r1 * 32 + col + 8];
            qa_lo[ks][0] = *(const u32*)&Ql[r0 * 32 + col];
            qa_lo[ks][1] = *(const u32*)&Ql[r1 * 32 + col];
            qa_lo[ks][2] = *(const u32*)&Ql[r0 * 32 + col + 8];
            qa_lo[ks][3] = *(const u32*)&Ql[r1 * 32 + col + 8];
        }
    }

    float O[4][4];
#pragma unroll
    for (int dt = 0; dt < 4; ++dt)
#pragma unroll
        for (int e = 0; e < 4; ++e) O[dt][e] = 0.f;
    float m0 = -1e30f, m1 = -1e30f, l0 = 0.f, l1 = 0.f;

    const int kbase = g * 32 + 2 * c;
    const int vbase = g * VT_PITCH + 2 * c;

    // ---- async stage of one 64-key chunk into buffer bi ----
    auto stage = [&](int ci, int bi) {
        char* base = smem_raw + bi * SB_STRIDE;
        const int t0 = ci * TT;
        u32 sb = (u32)__cvta_generic_to_shared(base);
        const char* srcKh = (const char*)(g_Khi + ((size_t)h * T_PAD + t0) * 32);
        const char* srcKl = (const char*)(g_Klo + ((size_t)h * T_PAD + t0) * 32);
#pragma unroll
        for (int it = 0; it < 2; ++it) {
            int idx = tid + it * 128;
            cpa16(sb + SB_KHI + idx * 16, srcKh + idx * 16);
            cpa16(sb + SB_KLO + idx * 16, srcKl + idx * 16);
        }
#pragma unroll
        for (int it = 0; it < 2; ++it) {
            int idx = tid + it * 128;
            int d = idx >> 3, s = idx & 7;
            size_t srcoff = ((size_t)(h * 32 + d) * T_PAD + t0) * 2 + s * 16;
            cpa16(sb + SB_VHI + d * 144 + s * 16, (const char*)g_Vthi + srcoff);
            cpa16(sb + SB_VLO + d * 144 + s * 16, (const char*)g_Vtlo + srcoff);
        }
        if (use_ov) {
#pragma unroll
            for (int it = 0; it < 8; ++it) {
                int idx = tid + it * 128;
                int r = idx >> 4, c4 = idx & 15;
                int qrow = min(qc * 64 + r, Q_LEN - 1);
                const char* src = (const char*)(g_OOV + (size_t)(b * Q_LEN + qrow) * T_PAD + t0) + c4 * 16;
                cpa16(sb + SB_OV + r * 288 + c4 * 16, src);
            }
        }
        CP_COMMIT();
    };

    stage(0, 0);

    for (int ci = 0; ci < NCH; ++ci) {
        const int t0 = ci * TT;
        const int bi = ci & 1;
        if (ci + 1 < NCH) { stage(ci + 1, bi ^ 1); CP_WAIT(1); }
        else              { CP_WAIT(0); }
        __syncthreads();

        if (warp_active) {
            char* base = smem_raw + bi * SB_STRIDE;
            const __half* sKhi = (const __half*)(base + SB_KHI);
            const __half* sKlo = (const __half*)(base + SB_KLO);
            const __half* sVhi = (const __half*)(base + SB_VHI);
            const __half* sVlo = (const __half*)(base + SB_VLO);
            const float*  sOV  = (const float*)(base + SB_OV);
            const float* so0 = sOV + (warp * 16 + g) * OV_PITCH + 2 * c;
            const float* so1 = so0 + 8 * OV_PITCH;

            // ---- S = Q K^T (8 n-tiles of 8 keys) ----
            float s[8][4];
#pragma unroll
            for (int j = 0; j < 8; ++j)
#pragma unroll
                for (int e = 0; e < 4; ++e) s[j][e] = 0.f;

            if (use_qk) {
#pragma unroll
                for (int j = 0; j < 8; ++j) {
#pragma unroll
                    for (int ks = 0; ks < 2; ++ks) {
                        const __half* kh = sKhi + j * 256 + kbase + 16 * ks;
                        const __half* kl = sKlo + j * 256 + kbase + 16 * ks;
                        u32 bh0 = *(const u32*)kh;
                        u32 bh1 = *(const u32*)(kh + 8);
                        u32 bl0 = *(const u32*)kl;
                        u32 bl1 = *(const u32*)(kl + 8);
                        mma16816(s[j], qa_hi[ks], bh0, bh1);
                        mma16816(s[j], qa_hi[ks], bl0, bl1);
                        mma16816(s[j], qa_lo[ks], bh0, bh1);
                    }
                }
            }
            if (use_ov) {
#pragma unroll
                for (int j = 0; j < 8; ++j) {
                    float2 o0 = *(const float2*)(so0 + 8 * j);
                    float2 o1 = *(const float2*)(so1 + 8 * j);
                    s[j][0] = fmaf(ap, o0.x, s[j][0]);
                    s[j][1] = fmaf(ap, o0.y, s[j][1]);
                    s[j][2] = fmaf(ap, o1.x, s[j][2]);
                    s[j][3] = fmaf(ap, o1.y, s[j][3]);
                }
            }
            if (t0 + TT > T_LEN) {
#pragma unroll
                for (int j = 0; j < 8; ++j) {
                    int t = t0 + 8 * j + 2 * c;
                    if (t >= T_LEN)     { s[j][0] = -1e30f; s[j][2] = -1e30f; }
                    if (t + 1 >= T_LEN) { s[j][1] = -1e30f; s[j][3] = -1e30f; }
                }
            }

            // ---- online softmax (log2 domain) ----
            float cm0 = s[0][0], cm1 = s[0][2];
#pragma unroll
            for (int j = 0; j < 8; ++j) {
                cm0 = fmaxf(cm0, fmaxf(s[j][0], s[j][1]));
                cm1 = fmaxf(cm1, fmaxf(s[j][2], s[j][3]));
            }
            cm0 = fmaxf(cm0, __shfl_xor_sync(0xffffffffu, cm0, 1));
            cm0 = fmaxf(cm0, __shfl_xor_sync(0xffffffffu, cm0, 2));
            cm1 = fmaxf(cm1, __shfl_xor_sync(0xffffffffu, cm1, 1));
            cm1 = fmaxf(cm1, __shfl_xor_sync(0xffffffffu, cm1, 2));
            float nm0 = fmaxf(m0, cm0), nm1 = fmaxf(m1, cm1);
            float rs0 = ex2(m0 - nm0), rs1 = ex2(m1 - nm1);
            m0 = nm0; m1 = nm1;
            l0 *= rs0; l1 *= rs1;
#pragma unroll
            for (int dt = 0; dt < 4; ++dt) {
                O[dt][0] *= rs0; O[dt][1] *= rs0;
                O[dt][2] *= rs1; O[dt][3] *= rs1;
            }
#pragma unroll
            for (int j = 0; j < 8; ++j) {
                s[j][0] = ex2(s[j][0] - m0);
                s[j][1] = ex2(s[j][1] - m0);
                s[j][2] = ex2(s[j][2] - m1);
                s[j][3] = ex2(s[j][3] - m1);
                l0 += s[j][0] + s[j][1];
                l1 += s[j][2] + s[j][3];
            }

            // ---- O += P V ----
#pragma unroll
            for (int ks = 0; ks < 4; ++ks) {
                const int j0 = 2 * ks, j1 = 2 * ks + 1;
                u32 pa_hi[4], pa_lo[4];
                pa_hi[0] = f2h2(s[j0][0], s[j0][1]);
                pa_hi[1] = f2h2(s[j0][2], s[j0][3]);
                pa_hi[2] = f2h2(s[j1][0], s[j1][1]);
                pa_hi[3] = f2h2(s[j1][2], s[j1][3]);
#pragma unroll
                for (int e = 0; e < 4; ++e) {
                    const int jj = (e < 2) ? j0 : j1;
                    const int base2 = (e & 1) ? 2 : 0;
                    float2 hf = h22f2(pa_hi[e]);
                    pa_lo[e] = f2h2(s[jj][base2] - hf.x, s[jj][base2 + 1] - hf.y);
                }
#pragma unroll
                for (int dt = 0; dt < 4; ++dt) {
                    const __half* vh = sVhi + dt * 8 * VT_PITCH + vbase + 16 * ks;
                    const __half* vl = sVlo + dt * 8 * VT_PITCH + vbase + 16 * ks;
                    u32 bh0 = *(const u32*)vh;
                    u32 bh1 = *(const u32*)(vh + 8);
                    u32 bl0 = *(const u32*)vl;
                    u32 bl1 = *(const u32*)(vl + 8);
                    mma16816(O[dt], pa_hi, bh0, bh1);
                    mma16816(O[dt], pa_hi, bl0, bl1);
                    mma16816(O[dt], pa_lo, bh0, bh1);
                }
            }
        }
        __syncthreads();   // all reads of buf bi done before it is re-staged
    }

    // ---- epilogue ----
    if (warp_active) {
        l0 += __shfl_xor_sync(0xffffffffu, l0, 1);
        l0 += __shfl_xor_sync(0xffffffffu, l0, 2);
        l1 += __shfl_xor_sync(0xffffffffu, l1, 1);
        l1 += __shfl_xor_sync(0xffffffffu, l1, 2);
        const float inv0 = 1.0f / l0, inv1 = 1.0f / l1;
        float* dstBase = g_AT + (size_t)(b * NHEAD + h) * Q_LEN * HEAD_DIM;
        if (q0 + g < Q_LEN) {
            float* d0 = dstBase + (size_t)(q0 + g) * HEAD_DIM + 2 * c;
#pragma unroll
            for (int dt = 0; dt < 4; ++dt)
                *(float2*)(d0 + 8 * dt) = make_float2(O[dt][0] * inv0, O[dt][1] * inv0);
        }
        if (q0 + g + 8 < Q_LEN) {
            float* d1 = dstBase + (size_t)(q0 + g + 8) * HEAD_DIM + 2 * c;
#pragma unroll
            for (int dt = 0; dt < 4; ++dt)
                *(float2*)(d1 + 8 * dt) = make_float2(O[dt][2] * inv1, O[dt][3] * inv1);
        }
    }
}

// ============================================================================
// Kernel 4: output projection + residual + LayerNorm (ROWS 16)
// ============================================================================
#define ROWS_P 16
__global__ __launch_bounds__(256, 2) void proj_kernel(
    const float* __restrict__ tgt, const float* __restrict__ bo,
    const float* __restrict__ ln_g, const float* __restrict__ ln_b, float* __restrict__ out)
{
    __shared__ float s_att[ROWS_P][D_MODEL];
    __shared__ float s_y[ROWS_P][D_MODEL];
    __shared__ float s_mu[ROWS_P], s_rs[ROWS_P];
    const int tid = threadIdx.x;
    const int r0 = blockIdx.x * ROWS_P;
    const int j = tid, head = j >> 5, lane = j & 31;

    for (int r = 0; r < ROWS_P; ++r) {
        int row = r0 + r, qi = row >> 5, b = row & 31;
        s_att[r][j] = g_AT[((size_t)((b * NHEAD) + head) * Q_LEN + qi) * HEAD_DIM + lane];
    }
    __syncthreads();

    u64 accA[ROWS_P], accB[ROWS_P];
#pragma unroll
    for (int r = 0; r < ROWS_P; ++r) { accA[r] = accB[r] = 0ull; }
    const ulonglong2* wop = ((const ulonglong2*)g_WoT4) + j;
#pragma unroll 2
    for (int c4 = 0; c4 < D_MODEL / 4; ++c4) {
        ulonglong2 w4 = wop[(size_t)c4 * D_MODEL];
#pragma unroll
        for (int r = 0; r < ROWS_P; ++r) {
            ulonglong2 x = *(const ulonglong2*)(&s_att[r][4 * c4]);
            accA[r] = fma2(x.x, w4.x, accA[r]);
            accB[r] = fma2(x.y, w4.y, accB[r]);
        }
    }

    const float boj = bo[j];
    for (int r = 0; r < ROWS_P; ++r) {
        int row = r0 + r;
        s_y[r][j] = hsum2(accA[r]) + hsum2(accB[r]) + boj + tgt[(size_t)row * D_MODEL + j];
    }
    __syncthreads();

    {
        const int w = tid >> 5, ln = tid & 31;
#pragma unroll
        for (int rr = 0; rr < 2; ++rr) {
            int r = 2 * w + rr;
            float sval = 0.f, sq = 0.f;
            for (int cc = ln; cc < D_MODEL; cc += 32) { float v = s_y[r][cc]; sval += v; sq += v * v; }
#pragma unroll
            for (int off = 16; off > 0; off >>= 1) {
                sval += __shfl_xor_sync(0xffffffffu, sval, off);
                sq   += __shfl_xor_sync(0xffffffffu, sq, off);
            }
            if (ln == 0) {
                float mu = sval * (1.0f / D_MODEL);
                s_mu[r] = mu;
                s_rs[r] = rsqrtf(sq * (1.0f / D_MODEL) - mu * mu + 1e-5f);
            }
        }
    }
    __syncthreads();

    const float gg = ln_g[j], bb = ln_b[j];
    for (int r = 0; r < ROWS_P; ++r) {
        int row = r0 + r;
        out[(size_t)row * D_MODEL + j] = (s_y[r][j] - s_mu[r]) * s_rs[r] * gg + bb;
    }
}

// ============================================================================
extern "C" void kernel_launch(void* const* d_in, const int* in_sizes, int n_in,
                              void* d_out, int out_size)
{
    const float* tgt  = (const float*)d_in[0];
    const float* text = (const float*)d_in[1];
    const float* qpos = (const float*)d_in[2];
    const float* oov  = (const float*)d_in[3];
    const float* Wq   = (const float*)d_in[4];
    const float* bq   = (const float*)d_in[5];
    const float* Wk   = (const float*)d_in[6];
    const float* bk   = (const float*)d_in[7];
    const float* Wv   = (const float*)d_in[8];
    const float* bv   = (const float*)d_in[9];
    const float* Wo   = (const float*)d_in[10];
    const float* bo   = (const float*)d_in[11];
    const float* lng  = (const float*)d_in[12];
    const float* lnb  = (const float*)d_in[13];
    const float* ls   = (const float*)d_in[14];
    float* out = (float*)d_out;

    pack_all_kernel<<<2048, 256>>>(Wq, Wk, Wv, Wo, oov);               // 1

    const int kv_smem = ROWS_KV * D_CLIP * (int)sizeof(float);         // 48 KB
    cudaFuncSetAttribute(kv_kernel, cudaFuncAttributeMaxDynamicSharedMemorySize, kv_smem);
    kv_kernel<<<dim3((T_LEN + ROWS_KV - 1) / ROWS_KV, 2), 256, kv_smem>>>(text, bk, bv, ls); // 2

    q_kernel<<<NROWS / ROWS_Q, 256>>>(tgt, qpos, bq);                  // 3

    const int att_smem = 2 * SB_STRIDE;                                // 71680 B
    cudaFuncSetAttribute(attn_kernel, cudaFuncAttributeMaxDynamicSharedMemorySize, att_smem);
    attn_kernel<<<dim3(NHEAD, BATCH, 2), 128, att_smem>>>();           // 4 <- profiled

    proj_kernel<<<NROWS / ROWS_P, 256>>>(tgt, bo, lng, lnb, out);      // 5
}